// round 14
// baseline (speedup 1.0000x reference)
#include <cuda_runtime.h>
#include <cuda_fp16.h>
#include <math.h>
#include <cstdint>

// B=32, T=512, N=1024, FT=16, FS=32, NCH=512, DIN=1024, H=1024
#define XROWS 32800
#define XTOT  33587200LL

// Scratch (device globals; zero-initialized). g_x1 rows >= 32800 stay zero.
__device__ __half g_x1[33024ull * 1024ull];   // gelu(embed)*scale, fp16
__device__ __half g_spk[16777216];            // fp16 spikes
__device__ __half g_we[524288];               // fp16 W_embed
__device__ __half g_wp[1048576];              // fp16 W_proj

__device__ __forceinline__ float gelu32(float x) {
    return 16.0f * x * (1.0f + erff(x * 0.7071067811865476f));
}
__device__ __forceinline__ void cp16(const __half* dst_s, const __half* src) {
    unsigned a = (unsigned)__cvta_generic_to_shared(dst_s);
    asm volatile("cp.async.cg.shared.global [%0], [%1], 16;" :: "r"(a), "l"(src));
}
__device__ __forceinline__ void ldsm4(unsigned& r0, unsigned& r1,
                                      unsigned& r2, unsigned& r3, uint32_t addr) {
    asm volatile("ldmatrix.sync.aligned.m8n8.x4.shared.b16 {%0,%1,%2,%3}, [%4];"
                 : "=r"(r0), "=r"(r1), "=r"(r2), "=r"(r3) : "r"(addr));
}
__device__ __forceinline__ uint2 pack4(float x, float y, float z, float w) {
    __half2 h01 = __floats2half2_rn(x, y);
    __half2 h23 = __floats2half2_rn(z, w);
    return make_uint2(*(unsigned*)&h01, *(unsigned*)&h23);
}
__device__ __forceinline__ void stcs2(float* p, float2 v) {
    asm volatile("st.global.cs.v2.f32 [%0], {%1, %2};" :: "l"(p), "f"(v.x), "f"(v.y));
}

// ---------------- pre-convert: spikes (ILP-8) + W_embed + cls ---------------
#define SPK4  4194304u
#define SPK4E 524288u
#define WE4   131072u
#define WP4   262144u
__global__ __launch_bounds__(256)
void convert_kernel(const float4* __restrict__ spk, const float4* __restrict__ we,
                    const float4* __restrict__ cls) {
    unsigned i = blockIdx.x * 256u + threadIdx.x;
    if (i < SPK4E) {
        #pragma unroll
        for (int r = 0; r < 8; r++) {
            unsigned j = i + r * SPK4E;
            float4 v = __ldcs(&spk[j]);
            ((uint2*)g_spk)[j] = pack4(v.x, v.y, v.z, v.w);
        }
    } else if (i < SPK4E + WE4) {
        unsigned j = i - SPK4E;
        float4 v = __ldcs(&we[j]);
        ((uint2*)g_we)[j] = pack4(v.x, v.y, v.z, v.w);
    } else {
        unsigned j = i - SPK4E - WE4;        // < 8192 : 32 batches x 256 uint2
        unsigned b = j >> 8, q = j & 255;
        float4 v = cls[q];
        ((uint2*)g_x1)[(size_t)b * 1025u * 256u + q] =
            pack4(gelu32(v.x), gelu32(v.y), gelu32(v.z), gelu32(v.w));
    }
}
#define CONV_BLOCKS ((SPK4E + WE4 + 8192u) / 256u)   // 2592

// ---------------- pipelined fp16 GEMM (LDSM + m16n8k16) ---------------------
// Block tile 128x128, 8 warps of 32(M)x64(N). K-chunk 64 halfs (128B/row),
// 3-stage cp.async, 2 CTAs/SM. smem stage: A[128][64]h then B[128][64]h.
// 16B chunk (row,ch) at byte row*128 + ((ch ^ (row&7)) << 4).
#define STG_BYTES 32768
#define SMEM_BYTES (3 * STG_BYTES)

template<int MODE>
__device__ __forceinline__ void issue_chunk(__half* smem, int s, int c,
                                            int bm, int bn, int tid) {
    constexpr int K = MODE ? 1024 : 512;
    const __half* Bsrc = MODE ? g_wp : g_we;
    __half* As = smem + s * (STG_BYTES / 2);
    __half* Bs = As + 8192;
    #pragma unroll
    for (int j = 0; j < 4; j++) {
        int ci = tid + j * 256;          // 1024 16B chunks per operand
        int row = ci >> 3, ch = ci & 7;
        int off = row * 64 + ((ch ^ (row & 7)) << 3);   // halfs
        const __half* srcA;
        if (MODE == 0) {
            int m = bm * 128 + row;
            int b = m >> 10, p = m & 1023, pt = p >> 5, ps = p & 31;
            srcA = g_spk + ((size_t)b << 19)
                         + ((size_t)((pt << 4) + 2 * c + (ch >> 2)) << 10)
                         + (ps << 5) + ((ch & 3) << 3);
        } else {
            srcA = g_x1 + ((size_t)(bm * 128 + row) << 10) + c * 64 + (ch << 3);
        }
        cp16(As + off, srcA);
        cp16(Bs + off, Bsrc + (size_t)(bn * 128 + row) * K + c * 64 + (ch << 3));
    }
}

__device__ __forceinline__ void compute_chunk(uint32_t As_b, uint32_t Bs_b,
                                              float acc[2][8][4],
                                              int wm, int wn, int lane) {
    const int l7 = lane & 7;
    const int l3 = (lane >> 3) & 1;
    const int l4 = (lane >> 4) & 1;
    #pragma unroll
    for (int ks = 0; ks < 4; ks++) {              // 4 x k16 steps = k64
        unsigned a[2][4];
        #pragma unroll
        for (int mi = 0; mi < 2; mi++) {
            const int r = wm + mi * 16 + l3 * 8 + l7;
            const int ch = (2 * ks + l4) ^ (r & 7);
            ldsm4(a[mi][0], a[mi][1], a[mi][2], a[mi][3],
                  As_b + r * 128 + (ch << 4));
        }
        unsigned bf[4][4];
        #pragma unroll
        for (int p = 0; p < 4; p++) {
            const int r = wn + p * 16 + l4 * 8 + l7;
            const int ch = (2 * ks + l3) ^ (r & 7);
            ldsm4(bf[p][0], bf[p][1], bf[p][2], bf[p][3],
                  Bs_b + r * 128 + (ch << 4));
        }
        #pragma unroll
        for (int p = 0; p < 4; p++) {
            #pragma unroll
            for (int sub = 0; sub < 2; sub++) {
                const int ni = 2 * p + sub;
                const unsigned b0 = bf[p][sub * 2];
                const unsigned b1 = bf[p][sub * 2 + 1];
                #pragma unroll
                for (int mi = 0; mi < 2; mi++) {
                    asm volatile(
                        "mma.sync.aligned.m16n8k16.row.col.f32.f16.f16.f32 "
                        "{%0,%1,%2,%3}, {%4,%5,%6,%7}, {%8,%9}, {%0,%1,%2,%3};"
                        : "+f"(acc[mi][ni][0]), "+f"(acc[mi][ni][1]),
                          "+f"(acc[mi][ni][2]), "+f"(acc[mi][ni][3])
                        : "r"(a[mi][0]), "r"(a[mi][1]),
                          "r"(a[mi][2]), "r"(a[mi][3]),
                          "r"(b0), "r"(b1));
                }
            }
        }
    }
}

template<int MODE>
__global__ __launch_bounds__(256, 2)
void fused_gemm(const float* __restrict__ bias, const float* __restrict__ pos,
                const float4* __restrict__ wp32,
                float* __restrict__ outp, int do_tail)
{
    constexpr int NC = MODE ? 16 : 8;    // K/64
    extern __shared__ __half smem[];
    const int tid  = threadIdx.x;
    const int bm   = blockIdx.y;
    const int bn   = blockIdx.x;
    const int warp = tid >> 5;
    const int lane = tid & 31;
    const int g = lane >> 2;
    const int t = lane & 3;
    const int wm = (warp & 3) << 5;
    const int wn = (warp >> 2) << 6;
    const uint32_t smem_b = (uint32_t)__cvta_generic_to_shared(smem);

    if (MODE == 0) {
        // Convert W_proj fp32 -> g_wp fp16, spread across GEMM1's 2048 CTAs.
        unsigned ci = (bm * 8 + bn) * 256u + tid;
        if (ci < WP4) {
            float4 v = __ldcs(&wp32[ci]);
            ((uint2*)g_wp)[ci] = pack4(v.x, v.y, v.z, v.w);
        }
    }
    if (MODE == 1 && do_tail) {
        int gid = (bm * 8 + bn) * 256 + tid;
        if (gid < XROWS) {
            outp[XTOT + gid] = 1.0f;
            outp[XTOT + XROWS + gid] = (float)(gid % 1025);
        }
    }

    float acc[2][8][4];
    #pragma unroll
    for (int i = 0; i < 2; i++)
        #pragma unroll
        for (int j = 0; j < 8; j++)
            #pragma unroll
            for (int e = 0; e < 4; e++) acc[i][j][e] = 0.0f;

    issue_chunk<MODE>(smem, 0, 0, bm, bn, tid);
    asm volatile("cp.async.commit_group;" ::: "memory");
    issue_chunk<MODE>(smem, 1, 1, bm, bn, tid);
    asm volatile("cp.async.commit_group;" ::: "memory");

    int s = 0;
    for (int c = 0; c < NC; c++) {
        asm volatile("cp.async.wait_group 1;" ::: "memory");
        __syncthreads();
        if (c + 2 < NC) {
            int s2 = s + 2; if (s2 >= 3) s2 -= 3;
            issue_chunk<MODE>(smem, s2, c + 2, bm, bn, tid);
        }
        asm volatile("cp.async.commit_group;" ::: "memory");
        const uint32_t As_b = smem_b + s * STG_BYTES;
        compute_chunk(As_b, As_b + 16384, acc, wm, wn, lane);
        if (++s == 3) s = 0;
    }

    // Epilogue. frag map: c0:(g,2t) c1:(g,2t+1) c2:(g+8,2t) c3:(g+8,2t+1)
    #pragma unroll
    for (int mi = 0; mi < 2; mi++) {
        const int m0 = bm * 128 + wm + (mi << 4) + g;
        const int m1 = m0 + 8;
        #pragma unroll
        for (int ni = 0; ni < 8; ni++) {
            const int n = bn * 128 + wn + (ni << 3) + (t << 1);
            const float2 bb = *(const float2*)(bias + n);
            if (MODE == 0) {
                {
                    const int b = m0 >> 10, p = m0 & 1023;
                    __half2 v = __floats2half2_rn(gelu32(acc[mi][ni][0] + bb.x),
                                                  gelu32(acc[mi][ni][1] + bb.y));
                    *(__half2*)&g_x1[((size_t)(b * 1025 + 1 + p) << 10) + n] = v;
                }
                {
                    const int b = m1 >> 10, p = m1 & 1023;
                    __half2 v = __floats2half2_rn(gelu32(acc[mi][ni][2] + bb.x),
                                                  gelu32(acc[mi][ni][3] + bb.y));
                    *(__half2*)&g_x1[((size_t)(b * 1025 + 1 + p) << 10) + n] = v;
                }
            } else {
                if (m0 < XROWS) {
                    const int p = m0 % 1025;
                    const float2 pv = *(const float2*)(pos + ((size_t)p << 10) + n);
                    stcs2(&outp[((size_t)m0 << 10) + n],
                          make_float2(acc[mi][ni][0] + bb.x + pv.x,
                                      acc[mi][ni][1] + bb.y + pv.y));
                }
                if (m1 < XROWS) {
                    const int p = m1 % 1025;
                    const float2 pv = *(const float2*)(pos + ((size_t)p << 10) + n);
                    stcs2(&outp[((size_t)m1 << 10) + n],
                          make_float2(acc[mi][ni][2] + bb.x + pv.x,
                                      acc[mi][ni][3] + bb.y + pv.y));
                }
            }
        }
    }
}

extern "C" void kernel_launch(void* const* d_in, const int* in_sizes, int n_in,
                              void* d_out, int out_size) {
    const float* spikes  = (const float*)d_in[0];
    const float* W_embed = (const float*)d_in[1];
    const float* b_embed = (const float*)d_in[2];
    const float* cls     = (const float*)d_in[3];
    const float* W_proj  = (const float*)d_in[4];
    const float* b_proj  = (const float*)d_in[5];
    const float* pos     = (const float*)d_in[6];
    float* outp = (float*)d_out;

    cudaFuncSetAttribute(fused_gemm<0>, cudaFuncAttributeMaxDynamicSharedMemorySize, SMEM_BYTES);
    cudaFuncSetAttribute(fused_gemm<1>, cudaFuncAttributeMaxDynamicSharedMemorySize, SMEM_BYTES);

    // 1) pre-convert spikes + W_embed + cls rows (W_proj deferred to GEMM1)
    convert_kernel<<<CONV_BLOCKS, 256>>>((const float4*)spikes, (const float4*)W_embed,
                                         (const float4*)cls);

    // 2) patchify + embed + gelu*scale -> g_x1 (+ hidden W_proj convert)
    fused_gemm<0><<<dim3(8, 256), 256, SMEM_BYTES>>>(b_embed, nullptr,
                                                     (const float4*)W_proj, nullptr, 0);

    // 3) proj + bias + pos_table -> d_out (+mask/stamp)
    int do_tail = ((long long)out_size >= XTOT + 2LL * XROWS) ? 1 : 0;
    fused_gemm<1><<<dim3(8, 257), 256, SMEM_BYTES>>>(b_proj, pos, nullptr, outp, do_tail);
}

// round 15
// speedup vs baseline: 1.0293x; 1.0293x over previous
#include <cuda_runtime.h>
#include <cuda_fp16.h>
#include <math.h>
#include <cstdint>

// B=32, T=512, N=1024, FT=16, FS=32, NCH=512, DIN=1024, H=1024
#define XROWS 32800
#define XTOT  33587200LL

// Scratch (device globals; zero-initialized). g_x1 rows >= 32800 stay zero.
__device__ __half g_x1[33024ull * 1024ull];   // gelu(embed)*scale, fp16
__device__ __half g_spk[16777216];            // fp16 spikes
__device__ __half g_we[524288];               // fp16 W_embed
__device__ __half g_wp[1048576];              // fp16 W_proj
__device__ int    g_cnt[33];                  // [0..31] per-batch gemm1 tiles, [32] wp

__device__ __forceinline__ float gelu32(float x) {
    return 16.0f * x * (1.0f + erff(x * 0.7071067811865476f));
}
__device__ __forceinline__ void cp16(const __half* dst_s, const __half* src) {
    unsigned a = (unsigned)__cvta_generic_to_shared(dst_s);
    asm volatile("cp.async.cg.shared.global [%0], [%1], 16;" :: "r"(a), "l"(src));
}
__device__ __forceinline__ void ldsm4(unsigned& r0, unsigned& r1,
                                      unsigned& r2, unsigned& r3, uint32_t addr) {
    asm volatile("ldmatrix.sync.aligned.m8n8.x4.shared.b16 {%0,%1,%2,%3}, [%4];"
                 : "=r"(r0), "=r"(r1), "=r"(r2), "=r"(r3) : "r"(addr));
}
__device__ __forceinline__ uint2 pack4(float x, float y, float z, float w) {
    __half2 h01 = __floats2half2_rn(x, y);
    __half2 h23 = __floats2half2_rn(z, w);
    return make_uint2(*(unsigned*)&h01, *(unsigned*)&h23);
}
__device__ __forceinline__ void stcs2(float* p, float2 v) {
    asm volatile("st.global.cs.v2.f32 [%0], {%1, %2};" :: "l"(p), "f"(v.x), "f"(v.y));
}

// ---------------- pre-convert: spikes (ILP-4) + W_embed + cls + cnt reset ---
#define SPK4  4194304u
#define SPK4Q 1048576u
#define WE4   131072u
#define WP4   262144u
__global__ __launch_bounds__(256)
void convert_kernel(const float4* __restrict__ spk, const float4* __restrict__ we,
                    const float4* __restrict__ cls) {
    if (blockIdx.x == 0 && threadIdx.x < 33) g_cnt[threadIdx.x] = 0;
    unsigned i = blockIdx.x * 256u + threadIdx.x;
    if (i < SPK4Q) {
        float4 v0 = __ldcs(&spk[i]);
        float4 v1 = __ldcs(&spk[i + SPK4Q]);
        float4 v2 = __ldcs(&spk[i + 2 * SPK4Q]);
        float4 v3 = __ldcs(&spk[i + 3 * SPK4Q]);
        ((uint2*)g_spk)[i]             = pack4(v0.x, v0.y, v0.z, v0.w);
        ((uint2*)g_spk)[i + SPK4Q]     = pack4(v1.x, v1.y, v1.z, v1.w);
        ((uint2*)g_spk)[i + 2 * SPK4Q] = pack4(v2.x, v2.y, v2.z, v2.w);
        ((uint2*)g_spk)[i + 3 * SPK4Q] = pack4(v3.x, v3.y, v3.z, v3.w);
    } else if (i < SPK4Q + WE4) {
        unsigned j = i - SPK4Q;
        float4 v = __ldcs(&we[j]);
        ((uint2*)g_we)[j] = pack4(v.x, v.y, v.z, v.w);
    } else {
        unsigned j = i - SPK4Q - WE4;        // < 8192 : 32 batches x 256 uint2
        unsigned b = j >> 8, q = j & 255;
        float4 v = cls[q];
        ((uint2*)g_x1)[(size_t)b * 1025u * 256u + q] =
            pack4(gelu32(v.x), gelu32(v.y), gelu32(v.z), gelu32(v.w));
    }
}
#define CONV_BLOCKS ((SPK4Q + WE4 + 8192u) / 256u)   // 4640

// ---------------- fused GEMM bodies (LDSM + m16n8k16) -----------------------
// Block tile 128x128, 8 warps of 32(M)x64(N). K-chunk 64 halfs (128B/row),
// 3-stage cp.async, 2 CTAs/SM. smem stage: A[128][64]h then B[128][64]h.
#define STG_BYTES 32768
#define SMEM_BYTES (3 * STG_BYTES)

template<int MODE>
__device__ __forceinline__ void issue_chunk(__half* smem, int s, int c,
                                            int bm, int bn, int tid) {
    constexpr int K = MODE ? 1024 : 512;
    const __half* Bsrc = MODE ? g_wp : g_we;
    __half* As = smem + s * (STG_BYTES / 2);
    __half* Bs = As + 8192;
    #pragma unroll
    for (int j = 0; j < 4; j++) {
        int ci = tid + j * 256;
        int row = ci >> 3, ch = ci & 7;
        int off = row * 64 + ((ch ^ (row & 7)) << 3);
        const __half* srcA;
        if (MODE == 0) {
            int m = bm * 128 + row;
            int b = m >> 10, p = m & 1023, pt = p >> 5, ps = p & 31;
            srcA = g_spk + ((size_t)b << 19)
                         + ((size_t)((pt << 4) + 2 * c + (ch >> 2)) << 10)
                         + (ps << 5) + ((ch & 3) << 3);
        } else {
            srcA = g_x1 + ((size_t)(bm * 128 + row) << 10) + c * 64 + (ch << 3);
        }
        cp16(As + off, srcA);
        cp16(Bs + off, Bsrc + (size_t)(bn * 128 + row) * K + c * 64 + (ch << 3));
    }
}

__device__ __forceinline__ void compute_chunk(uint32_t As_b, uint32_t Bs_b,
                                              float acc[2][8][4],
                                              int wm, int wn, int lane) {
    const int l7 = lane & 7;
    const int l3 = (lane >> 3) & 1;
    const int l4 = (lane >> 4) & 1;
    #pragma unroll
    for (int ks = 0; ks < 4; ks++) {
        unsigned a[2][4];
        #pragma unroll
        for (int mi = 0; mi < 2; mi++) {
            const int r = wm + mi * 16 + l3 * 8 + l7;
            const int ch = (2 * ks + l4) ^ (r & 7);
            ldsm4(a[mi][0], a[mi][1], a[mi][2], a[mi][3],
                  As_b + r * 128 + (ch << 4));
        }
        unsigned bf[4][4];
        #pragma unroll
        for (int p = 0; p < 4; p++) {
            const int r = wn + p * 16 + l4 * 8 + l7;
            const int ch = (2 * ks + l3) ^ (r & 7);
            ldsm4(bf[p][0], bf[p][1], bf[p][2], bf[p][3],
                  Bs_b + r * 128 + (ch << 4));
        }
        #pragma unroll
        for (int p = 0; p < 4; p++) {
            #pragma unroll
            for (int sub = 0; sub < 2; sub++) {
                const int ni = 2 * p + sub;
                const unsigned b0 = bf[p][sub * 2];
                const unsigned b1 = bf[p][sub * 2 + 1];
                #pragma unroll
                for (int mi = 0; mi < 2; mi++) {
                    asm volatile(
                        "mma.sync.aligned.m16n8k16.row.col.f32.f16.f16.f32 "
                        "{%0,%1,%2,%3}, {%4,%5,%6,%7}, {%8,%9}, {%0,%1,%2,%3};"
                        : "+f"(acc[mi][ni][0]), "+f"(acc[mi][ni][1]),
                          "+f"(acc[mi][ni][2]), "+f"(acc[mi][ni][3])
                        : "r"(a[mi][0]), "r"(a[mi][1]),
                          "r"(a[mi][2]), "r"(a[mi][3]),
                          "r"(b0), "r"(b1));
                }
            }
        }
    }
}

template<int MODE>
__device__ __forceinline__ void gemm_body(int bm, int bn, int tid,
                                          const float* __restrict__ bias,
                                          const float* __restrict__ pos,
                                          float* __restrict__ outp,
                                          __half* smem)
{
    constexpr int NC = MODE ? 16 : 8;
    const int warp = tid >> 5;
    const int lane = tid & 31;
    const int g = lane >> 2;
    const int t = lane & 3;
    const int wm = (warp & 3) << 5;
    const int wn = (warp >> 2) << 6;
    const uint32_t smem_b = (uint32_t)__cvta_generic_to_shared(smem);

    float acc[2][8][4];
    #pragma unroll
    for (int i = 0; i < 2; i++)
        #pragma unroll
        for (int j = 0; j < 8; j++)
            #pragma unroll
            for (int e = 0; e < 4; e++) acc[i][j][e] = 0.0f;

    issue_chunk<MODE>(smem, 0, 0, bm, bn, tid);
    asm volatile("cp.async.commit_group;" ::: "memory");
    issue_chunk<MODE>(smem, 1, 1, bm, bn, tid);
    asm volatile("cp.async.commit_group;" ::: "memory");

    int s = 0;
    for (int c = 0; c < NC; c++) {
        asm volatile("cp.async.wait_group 1;" ::: "memory");
        __syncthreads();
        if (c + 2 < NC) {
            int s2 = s + 2; if (s2 >= 3) s2 -= 3;
            issue_chunk<MODE>(smem, s2, c + 2, bm, bn, tid);
        }
        asm volatile("cp.async.commit_group;" ::: "memory");
        const uint32_t As_b = smem_b + s * STG_BYTES;
        compute_chunk(As_b, As_b + 16384, acc, wm, wn, lane);
        if (++s == 3) s = 0;
    }

    #pragma unroll
    for (int mi = 0; mi < 2; mi++) {
        const int m0 = bm * 128 + wm + (mi << 4) + g;
        const int m1 = m0 + 8;
        #pragma unroll
        for (int ni = 0; ni < 8; ni++) {
            const int n = bn * 128 + wn + (ni << 3) + (t << 1);
            const float2 bb = *(const float2*)(bias + n);
            if (MODE == 0) {
                {
                    const int b = m0 >> 10, p = m0 & 1023;
                    __half2 v = __floats2half2_rn(gelu32(acc[mi][ni][0] + bb.x),
                                                  gelu32(acc[mi][ni][1] + bb.y));
                    *(__half2*)&g_x1[((size_t)(b * 1025 + 1 + p) << 10) + n] = v;
                }
                {
                    const int b = m1 >> 10, p = m1 & 1023;
                    __half2 v = __floats2half2_rn(gelu32(acc[mi][ni][2] + bb.x),
                                                  gelu32(acc[mi][ni][3] + bb.y));
                    *(__half2*)&g_x1[((size_t)(b * 1025 + 1 + p) << 10) + n] = v;
                }
            } else {
                if (m0 < XROWS) {
                    const int p = m0 % 1025;
                    const float2 pv = *(const float2*)(pos + ((size_t)p << 10) + n);
                    stcs2(&outp[((size_t)m0 << 10) + n],
                          make_float2(acc[mi][ni][0] + bb.x + pv.x,
                                      acc[mi][ni][1] + bb.y + pv.y));
                }
                if (m1 < XROWS) {
                    const int p = m1 % 1025;
                    const float2 pv = *(const float2*)(pos + ((size_t)p << 10) + n);
                    stcs2(&outp[((size_t)m1 << 10) + n],
                          make_float2(acc[mi][ni][2] + bb.x + pv.x,
                                      acc[mi][ni][3] + bb.y + pv.y));
                }
            }
        }
    }
}

// Merged kernel: CTAs 0..2047 = GEMM1 (producers), 2048..4103 = GEMM2.
__global__ __launch_bounds__(256, 2)
void mega_gemm(const float* __restrict__ b_embed, const float* __restrict__ b_proj,
               const float* __restrict__ pos, const float4* __restrict__ wp32,
               float* __restrict__ outp, int do_tail)
{
    extern __shared__ __half smem[];
    const int bid = blockIdx.x;
    const int tid = threadIdx.x;

    if (bid < 2048) {
        // ---- GEMM1 producer path ----
        if (bid < 1024) {
            unsigned ci = bid * 256u + tid;     // < WP4
            float4 v = __ldcs(&wp32[ci]);
            ((uint2*)g_wp)[ci] = pack4(v.x, v.y, v.z, v.w);
            __threadfence();
            __syncthreads();
            if (tid == 0) atomicAdd(&g_cnt[32], 1);
        }
        gemm_body<0>(bid >> 3, bid & 7, tid, b_embed, nullptr, outp, smem);
        __syncthreads();                        // all epilogue stores issued
        if (tid == 0) {
            __threadfence();                    // release
            atomicAdd(&g_cnt[bid >> 6], 1);     // batch = (bid>>3)>>3
        }
    } else {
        // ---- GEMM2 consumer path ----
        const int id2 = bid - 2048;
        const int bm = id2 >> 3, bn = id2 & 7;
        if (do_tail) {
            int gid = id2 * 256 + tid;
            if (gid < XROWS) {
                outp[XTOT + gid] = 1.0f;
                outp[XTOT + XROWS + gid] = (float)(gid % 1025);
            }
        }
        int b0 = (bm * 128) / 1025;
        int b1 = (bm * 128 + 127) / 1025; if (b1 > 31) b1 = 31;
        volatile int* vc = (volatile int*)g_cnt;
        while (vc[32] < 1024) __nanosleep(128);
        while (vc[b0] < 64)   __nanosleep(128);
        while (vc[b1] < 64)   __nanosleep(128);
        __threadfence();                        // acquire
        __syncthreads();
        gemm_body<1>(bm, bn, tid, b_proj, pos, outp, smem);
    }
}

extern "C" void kernel_launch(void* const* d_in, const int* in_sizes, int n_in,
                              void* d_out, int out_size) {
    const float* spikes  = (const float*)d_in[0];
    const float* W_embed = (const float*)d_in[1];
    const float* b_embed = (const float*)d_in[2];
    const float* cls     = (const float*)d_in[3];
    const float* W_proj  = (const float*)d_in[4];
    const float* b_proj  = (const float*)d_in[5];
    const float* pos     = (const float*)d_in[6];
    float* outp = (float*)d_out;

    cudaFuncSetAttribute(mega_gemm, cudaFuncAttributeMaxDynamicSharedMemorySize, SMEM_BYTES);

    // 1) pre-convert spikes + W_embed + cls rows; reset ready-counters
    convert_kernel<<<CONV_BLOCKS, 256>>>((const float4*)spikes, (const float4*)W_embed,
                                         (const float4*)cls);

    // 2) merged GEMM1 + GEMM2 with per-batch ready-counter handoff
    int do_tail = ((long long)out_size >= XTOT + 2LL * XROWS) ? 1 : 0;
    mega_gemm<<<4104, 256, SMEM_BYTES>>>(b_embed, b_proj, pos,
                                         (const float4*)W_proj, outp, do_tail);
}